// round 14
// baseline (speedup 1.0000x reference)
#include <cuda_runtime.h>
#include <stdint.h>

// Fixed shapes
#define BS_   16
#define A_    33600
#define G_    64
#define NC_   80
#define TPB   256
#define APT   4                                   // anchors per thread in k_iou
#define NBI_  ((A_ + TPB*APT - 1) / (TPB*APT))    // 33 iou blocks per batch
#define NB_   ((A_ + TPB - 1) / TPB)              // 132 assign blocks per batch
#define IOU_T 0.3f
#define EPS_  1e-9f

// Output layout: float32 value-concat of (labels, bboxes, scores, fg_mask, tgt_idx)
#define OFF_LAB  0
#define OFF_BBOX (BS_*A_)                 //   537600
#define OFF_SC   (BS_*A_*5)               //  2688000
#define OFF_FG   (OFF_SC + BS_*A_*NC_)    // 45696000
#define OFF_TGT  (OFF_FG + BS_*A_)        // 46233600

// Scratch (static device globals — no allocation anywhere)
__device__ float         g_maxiou[BS_*A_];
__device__ unsigned char g_arg[BS_*A_];
__device__ int           g_bany[BS_*NBI_];
__device__ float         g_thr[BS_];
__device__ int           g_mode[BS_];

__device__ __forceinline__ void ins3(float& t0, float& t1, float& t2, float v) {
    if (v > t0)      { t2 = t1; t1 = t0; t0 = v; }
    else if (v > t1) { t2 = t1; t1 = v; }
    else if (v > t2) { t2 = v; }
}

// ---------------- Kernel 1: IoU + per-anchor max/argmax + per-block any-flag ----------------
__global__ __launch_bounds__(TPB) void k_iou(const float* __restrict__ pd_bboxes,
                                             const float* __restrict__ gt_bboxes,
                                             const int*   __restrict__ mask_gt) {
    const int b   = blockIdx.y;
    const int tid = threadIdx.x;
    const int abase = blockIdx.x * (TPB*APT) + tid;

    __shared__ float4 sbox[G_];     // x1,y1,x2,y2
    __shared__ float2 sav[G_];      // area, valid
    if (tid < G_) {
        const int g = tid;
        float4 p = reinterpret_cast<const float4*>(gt_bboxes)[b*G_ + g];
        sbox[g] = p;
        sav[g]  = make_float2((p.z - p.x) * (p.w - p.y),
                              mask_gt[b*G_ + g] ? 1.0f : 0.0f);
    }

    // Load anchors before the sync to overlap with GT tile fill
    bool   va[APT];
    float4 pb[APT];
    float  q[APT];
    #pragma unroll
    for (int k = 0; k < APT; k++) {
        int a = abase + k*TPB;
        va[k] = (a < A_);
        pb[k] = va[k] ? reinterpret_cast<const float4*>(pd_bboxes)[b*A_ + a]
                      : make_float4(0.f,0.f,0.f,0.f);
        q[k]  = (pb[k].z - pb[k].x) * (pb[k].w - pb[k].y);
    }
    __syncthreads();

    float best[APT];
    int   bi[APT];
    #pragma unroll
    for (int k = 0; k < APT; k++) { best[k] = -1.0f; bi[k] = 0; }

    #pragma unroll 2
    for (int g = 0; g < G_; g++) {
        float4 bx = sbox[g];
        float2 av = sav[g];
        #pragma unroll
        for (int k = 0; k < APT; k++) {
            float iw = fmaxf(fminf(bx.z, pb[k].z) - fmaxf(bx.x, pb[k].x), 0.0f);
            float ih = fmaxf(fminf(bx.w, pb[k].w) - fmaxf(bx.y, pb[k].y), 0.0f);
            float inter = iw * ih;
            float iou = inter / (av.x + q[k] - inter + EPS_);
            float ov  = iou * av.y;                // overlaps = iou * valid
            if (ov > best[k]) { best[k] = ov; bi[k] = g; }   // first-occurrence argmax
        }
    }

    int any = 0;
    #pragma unroll
    for (int k = 0; k < APT; k++) {
        int a = abase + k*TPB;
        if (va[k]) {
            g_maxiou[b*A_ + a] = best[k];
            g_arg[b*A_ + a]    = (unsigned char)bi[k];
            any |= (best[k] > IOU_T) ? 1 : 0;
        }
    }
    int r = __syncthreads_or(any);
    if (tid == 0) g_bany[b*NBI_ + blockIdx.x] = r;
}

// ---------------- Kernel 2: per-batch mode decision + (cold) fallback threshold ----------------
// Hot path: merge 33 flags + 64 valids -> mode, thr = IOU_T.  Cold path (mode=1, which
// requires NO anchor in the whole batch above 0.3 — effectively never with this data):
// this block recomputes the batch's top-3 valid overlap itself.
__global__ __launch_bounds__(TPB) void k_fallback(const float* __restrict__ pd_bboxes,
                                                  const float* __restrict__ gt_bboxes,
                                                  const int*   __restrict__ mask_gt) {
    const int b = blockIdx.x, tid = threadIdx.x;

    int any = (tid < NBI_) ? g_bany[b*NBI_ + tid] : 0;
    int hv  = (tid < G_)   ? (mask_gt[b*G_ + tid] != 0) : 0;
    int fgany = __syncthreads_or(any);
    int hasv  = __syncthreads_or(hv);
    const bool need_fb = (!fgany) && hasv;        // block-uniform

    if (tid == 0) {
        g_mode[b] = need_fb ? 1 : 0;
        g_thr[b]  = IOU_T;
    }
    if (!need_fb) return;                         // uniform exit — hot path ends here

    // ---- cold path: batch-wide top-3 of (iou * valid) ----
    __shared__ float4 sbox[G_];
    __shared__ float2 sav[G_];
    if (tid < G_) {
        const int g = tid;
        float4 p = reinterpret_cast<const float4*>(gt_bboxes)[b*G_ + g];
        sbox[g] = p;
        sav[g]  = make_float2((p.z - p.x) * (p.w - p.y),
                              mask_gt[b*G_ + g] ? 1.0f : 0.0f);
    }
    __syncthreads();

    const float NEGINF = __int_as_float(0xff800000);
    float t0 = NEGINF, t1 = NEGINF, t2 = NEGINF;
    for (int a = tid; a < A_; a += TPB) {
        float4 pb = reinterpret_cast<const float4*>(pd_bboxes)[b*A_ + a];
        float q = (pb.z - pb.x) * (pb.w - pb.y);
        #pragma unroll 4
        for (int g = 0; g < G_; g++) {
            float4 bx = sbox[g];
            float2 av = sav[g];
            float iw = fmaxf(fminf(bx.z, pb.z) - fmaxf(bx.x, pb.x), 0.0f);
            float ih = fmaxf(fminf(bx.w, pb.w) - fmaxf(bx.y, pb.y), 0.0f);
            float inter = iw * ih;
            float iou = inter / (av.x + q - inter + EPS_);
            float ov  = iou * av.y;
            // Unconditional insert is safe: overlaps >= 0; any valid GT contributes
            // A_ >= 3 nonneg values, so invalid-GT zeros never change the 3rd max.
            ins3(t0, t1, t2, ov);
        }
    }

    __shared__ float s0[TPB], s1[TPB], s2[TPB];
    s0[tid] = t0; s1[tid] = t1; s2[tid] = t2;
    __syncthreads();
    for (int s = TPB/2; s > 0; s >>= 1) {
        if (tid < s) {
            float a0 = s0[tid], a1 = s1[tid], a2 = s2[tid];
            ins3(a0, a1, a2, s0[tid + s]);
            ins3(a0, a1, a2, s1[tid + s]);
            ins3(a0, a1, a2, s2[tid + s]);
            s0[tid] = a0; s1[tid] = a1; s2[tid] = a2;
        }
        __syncthreads();
    }
    if (tid == 0) g_thr[b] = s2[0];               // min_iou = 3rd-largest valid overlap
}

// ---------------- Kernel 3: fused assignment + all outputs ----------------
__global__ __launch_bounds__(TPB) void k_assign_scores(const int*   __restrict__ gt_labels,
                                                       const float* __restrict__ gt_bboxes,
                                                       const int*   __restrict__ mask_gt,
                                                       float*       __restrict__ out) {
    const int b   = blockIdx.y;
    const int tid = threadIdx.x;
    const int abase = blockIdx.x * TPB;
    const int a = abase + tid;

    __shared__ unsigned s_info[TPB];

    // Phase 1: per-anchor assignment + small outputs
    unsigned info = 0;
    if (a < A_) {
        const int i = b*A_ + a;
        float mx  = g_maxiou[i];
        int   tgt = g_arg[i];
        float thr = g_thr[b];
        bool  fg  = g_mode[b] ? (mx >= thr) : (mx > thr);

        const int gi = b*G_ + tgt;
        bool mk  = fg && (mask_gt[gi] != 0);
        int  lab = gt_labels[gi];

        out[OFF_LAB + i] = mk ? (float)lab : 80.0f;       // BG_IDX = 80
        float4 bb = mk ? reinterpret_cast<const float4*>(gt_bboxes)[gi]
                       : make_float4(0.f, 0.f, 0.f, 0.f);
        reinterpret_cast<float4*>(out + OFF_BBOX)[i] = bb;
        out[OFF_FG  + i] = fg ? 1.0f : 0.0f;
        out[OFF_TGT + i] = (float)tgt;
        info = mk ? (0x100u | (unsigned)lab) : 0u;
    }
    s_info[tid] = info;
    __syncthreads();

    // Phase 2: one-hot scores, coalesced float4 stores over the block's contiguous region.
    // Incremental (local, q) bookkeeping instead of div/mod by 20 per iteration.
    const int nv = min(TPB, A_ - abase);                  // valid anchors in this block
    const long long i0 = (long long)b*A_ + abase;         // first global anchor
    float4* sc4 = reinterpret_cast<float4*>(out + OFF_SC) + i0 * (NC_/4);
    const int total = nv * (NC_/4);
    int local = tid / (NC_/4);
    int q     = tid - local * (NC_/4);
    for (int k = tid; k < total; k += TPB) {
        unsigned inf = s_info[local];
        int lb = (inf & 0x100u) ? (int)(inf & 0xFFu) : -1;
        int base = q * 4;
        float4 v;
        v.x = (lb == base    ) ? 1.0f : 0.0f;
        v.y = (lb == base + 1) ? 1.0f : 0.0f;
        v.z = (lb == base + 2) ? 1.0f : 0.0f;
        v.w = (lb == base + 3) ? 1.0f : 0.0f;
        sc4[k] = v;
        // advance (local, q) by TPB positions in the (anchor, quad) space
        local += TPB / (NC_/4);                            // 256/20 = 12
        q     += TPB - (TPB / (NC_/4)) * (NC_/4);          // remainder 16
        if (q >= (NC_/4)) { q -= (NC_/4); local += 1; }
    }
}

extern "C" void kernel_launch(void* const* d_in, const int* in_sizes, int n_in,
                              void* d_out, int out_size) {
    // metadata order: pd_scores, pd_bboxes, anc_points, gt_labels, gt_bboxes, mask_gt
    const float* pd_bboxes = (const float*)d_in[1];
    const int*   gt_labels = (const int*)d_in[3];   // int64 -> int32 by harness
    const float* gt_bboxes = (const float*)d_in[4];
    const int*   mask_gt   = (const int*)d_in[5];
    float* out = (float*)d_out;

    dim3 gi(NBI_, BS_), ga(NB_, BS_);
    k_iou<<<gi, TPB>>>(pd_bboxes, gt_bboxes, mask_gt);
    k_fallback<<<BS_, TPB>>>(pd_bboxes, gt_bboxes, mask_gt);
    k_assign_scores<<<ga, TPB>>>(gt_labels, gt_bboxes, mask_gt, out);
}

// round 15
// speedup vs baseline: 1.9494x; 1.9494x over previous
#include <cuda_runtime.h>
#include <stdint.h>

// Fixed shapes
#define BS_   16
#define A_    33600
#define G_    64
#define NC_   80
#define TPB   256
#define APT   2                                   // anchors per thread in k_iou
#define NBI_  ((A_ + TPB*APT - 1) / (TPB*APT))    // 66 iou blocks per batch
#define NB_   ((A_ + TPB - 1) / TPB)              // 132 assign blocks per batch
#define IOU_T 0.3f
#define EPS_  1e-9f

// Output layout: float32 value-concat of (labels, bboxes, scores, fg_mask, tgt_idx)
#define OFF_LAB  0
#define OFF_BBOX (BS_*A_)                 //   537600
#define OFF_SC   (BS_*A_*5)               //  2688000
#define OFF_FG   (OFF_SC + BS_*A_*NC_)    // 45696000
#define OFF_TGT  (OFF_FG + BS_*A_)        // 46233600

// Scratch (static device globals — no allocation anywhere)
__device__ float         g_maxiou[BS_*A_];
__device__ unsigned char g_arg[BS_*A_];
__device__ int           g_bany[BS_*NBI_];
__device__ float         g_thr[BS_];
__device__ int           g_mode[BS_];

__device__ __forceinline__ void ins3(float& t0, float& t1, float& t2, float v) {
    if (v > t0)      { t2 = t1; t1 = t0; t0 = v; }
    else if (v > t1) { t2 = t1; t1 = v; }
    else if (v > t2) { t2 = v; }
}

// ---------------- Kernel 1: IoU argmax (division-free mainloop) ----------------
// Invalid GTs are stored as degenerate boxes => intersection clamps to 0 => their
// "overlap ratio" is exactly 0, identical to the reference's iou * valid.
// Argmax is tracked as a fraction (best_inter, best_union); the single division
// per anchor happens in the epilogue, rounding identically to the reference's
// per-pair division for the selected pair.
__global__ __launch_bounds__(TPB) void k_iou(const float* __restrict__ pd_bboxes,
                                             const float* __restrict__ gt_bboxes,
                                             const int*   __restrict__ mask_gt) {
    const int b   = blockIdx.y;
    const int tid = threadIdx.x;
    const int a0  = blockIdx.x * (TPB*APT) + tid;
    const int a1  = a0 + TPB;

    __shared__ float4 sbox[G_];     // x1,y1,x2,y2 (degenerate if invalid)
    __shared__ float  sarea[G_];    // gt area (0 if invalid)
    if (tid < G_) {
        const int g = tid;
        float4 p = reinterpret_cast<const float4*>(gt_bboxes)[b*G_ + g];
        if (mask_gt[b*G_ + g] != 0) {
            sbox[g]  = p;
            sarea[g] = (p.z - p.x) * (p.w - p.y);
        } else {
            sbox[g]  = make_float4(0.f, 0.f, -1.f, -1.f);  // forces iw <= 0
            sarea[g] = 0.f;                                 // union = q + eps > 0
        }
    }

    const bool va0 = (a0 < A_), va1 = (a1 < A_);
    float4 p0 = va0 ? reinterpret_cast<const float4*>(pd_bboxes)[b*A_ + a0]
                    : make_float4(0.f,0.f,0.f,0.f);
    float4 p1 = va1 ? reinterpret_cast<const float4*>(pd_bboxes)[b*A_ + a1]
                    : make_float4(0.f,0.f,0.f,0.f);
    float q0 = (p0.z - p0.x) * (p0.w - p0.y);
    float q1 = (p1.z - p1.x) * (p1.w - p1.y);
    __syncthreads();

    // best ratio as fraction; init ratio = -1 so g=0 always wins (ratios >= 0)
    float bi0 = -1.0f, bu0 = 1.0f;  int idx0 = 0;
    float bi1 = -1.0f, bu1 = 1.0f;  int idx1 = 0;

    #pragma unroll 4
    for (int g = 0; g < G_; g++) {
        float4 bx = sbox[g];
        float  ar = sarea[g];
        // anchor 0
        {
            float iw = fmaxf(fminf(bx.z, p0.z) - fmaxf(bx.x, p0.x), 0.0f);
            float ih = fmaxf(fminf(bx.w, p0.w) - fmaxf(bx.y, p0.y), 0.0f);
            float inter = iw * ih;
            float un = ar + q0 - inter + EPS_;     // ((a1+a2)-inter)+eps, ref association
            if (inter * bu0 > bi0 * un) { bi0 = inter; bu0 = un; idx0 = g; }
        }
        // anchor 1
        {
            float iw = fmaxf(fminf(bx.z, p1.z) - fmaxf(bx.x, p1.x), 0.0f);
            float ih = fmaxf(fminf(bx.w, p1.w) - fmaxf(bx.y, p1.y), 0.0f);
            float inter = iw * ih;
            float un = ar + q1 - inter + EPS_;
            if (inter * bu1 > bi1 * un) { bi1 = inter; bu1 = un; idx1 = g; }
        }
    }

    int any = 0;
    if (va0) {
        float mx = bi0 / bu0;                      // one IEEE div per anchor
        g_maxiou[b*A_ + a0] = mx;
        g_arg[b*A_ + a0]    = (unsigned char)idx0;
        any |= (mx > IOU_T) ? 1 : 0;
    }
    if (va1) {
        float mx = bi1 / bu1;
        g_maxiou[b*A_ + a1] = mx;
        g_arg[b*A_ + a1]    = (unsigned char)idx1;
        any |= (mx > IOU_T) ? 1 : 0;
    }
    int r = __syncthreads_or(any);
    if (tid == 0) g_bany[b*NBI_ + blockIdx.x] = r;
}

// ---------------- Kernel 2: per-batch mode decision + (cold) fallback threshold ----------------
__global__ __launch_bounds__(TPB) void k_fallback(const float* __restrict__ pd_bboxes,
                                                  const float* __restrict__ gt_bboxes,
                                                  const int*   __restrict__ mask_gt) {
    const int b = blockIdx.x, tid = threadIdx.x;

    int any = (tid < NBI_) ? g_bany[b*NBI_ + tid] : 0;
    int hv  = (tid < G_)   ? (mask_gt[b*G_ + tid] != 0) : 0;
    int fgany = __syncthreads_or(any);
    int hasv  = __syncthreads_or(hv);
    const bool need_fb = (!fgany) && hasv;        // block-uniform

    if (tid == 0) {
        g_mode[b] = need_fb ? 1 : 0;
        g_thr[b]  = IOU_T;
    }
    if (!need_fb) return;                         // uniform exit — hot path ends here

    // ---- cold path: batch-wide top-3 of (iou * valid), division-based (exact ref math) ----
    __shared__ float4 sbox[G_];
    __shared__ float2 sav[G_];
    if (tid < G_) {
        const int g = tid;
        float4 p = reinterpret_cast<const float4*>(gt_bboxes)[b*G_ + g];
        sbox[g] = p;
        sav[g]  = make_float2((p.z - p.x) * (p.w - p.y),
                              mask_gt[b*G_ + g] ? 1.0f : 0.0f);
    }
    __syncthreads();

    const float NEGINF = __int_as_float(0xff800000);
    float t0 = NEGINF, t1 = NEGINF, t2 = NEGINF;
    for (int a = tid; a < A_; a += TPB) {
        float4 pb = reinterpret_cast<const float4*>(pd_bboxes)[b*A_ + a];
        float q = (pb.z - pb.x) * (pb.w - pb.y);
        #pragma unroll 4
        for (int g = 0; g < G_; g++) {
            float4 bx = sbox[g];
            float2 av = sav[g];
            float iw = fmaxf(fminf(bx.z, pb.z) - fmaxf(bx.x, pb.x), 0.0f);
            float ih = fmaxf(fminf(bx.w, pb.w) - fmaxf(bx.y, pb.y), 0.0f);
            float inter = iw * ih;
            float iou = inter / (av.x + q - inter + EPS_);
            float ov  = iou * av.y;
            // Unconditional insert is safe: overlaps >= 0; any valid GT contributes
            // A_ >= 3 nonneg values, so invalid-GT zeros never change the 3rd max.
            ins3(t0, t1, t2, ov);
        }
    }

    __shared__ float s0[TPB], s1[TPB], s2[TPB];
    s0[tid] = t0; s1[tid] = t1; s2[tid] = t2;
    __syncthreads();
    for (int s = TPB/2; s > 0; s >>= 1) {
        if (tid < s) {
            float a0 = s0[tid], a1 = s1[tid], a2 = s2[tid];
            ins3(a0, a1, a2, s0[tid + s]);
            ins3(a0, a1, a2, s1[tid + s]);
            ins3(a0, a1, a2, s2[tid + s]);
            s0[tid] = a0; s1[tid] = a1; s2[tid] = a2;
        }
        __syncthreads();
    }
    if (tid == 0) g_thr[b] = s2[0];               // min_iou = 3rd-largest valid overlap
}

// ---------------- Kernel 3: fused assignment + all outputs ----------------
__global__ __launch_bounds__(TPB) void k_assign_scores(const int*   __restrict__ gt_labels,
                                                       const float* __restrict__ gt_bboxes,
                                                       const int*   __restrict__ mask_gt,
                                                       float*       __restrict__ out) {
    const int b   = blockIdx.y;
    const int tid = threadIdx.x;
    const int abase = blockIdx.x * TPB;
    const int a = abase + tid;

    __shared__ unsigned s_info[TPB];

    // Phase 1: per-anchor assignment + small outputs
    unsigned info = 0;
    if (a < A_) {
        const int i = b*A_ + a;
        float mx  = g_maxiou[i];
        int   tgt = g_arg[i];
        float thr = g_thr[b];
        bool  fg  = g_mode[b] ? (mx >= thr) : (mx > thr);

        const int gi = b*G_ + tgt;
        bool mk  = fg && (mask_gt[gi] != 0);
        int  lab = gt_labels[gi];

        out[OFF_LAB + i] = mk ? (float)lab : 80.0f;       // BG_IDX = 80
        float4 bb = mk ? reinterpret_cast<const float4*>(gt_bboxes)[gi]
                       : make_float4(0.f, 0.f, 0.f, 0.f);
        reinterpret_cast<float4*>(out + OFF_BBOX)[i] = bb;
        out[OFF_FG  + i] = fg ? 1.0f : 0.0f;
        out[OFF_TGT + i] = (float)tgt;
        info = mk ? (0x100u | (unsigned)lab) : 0u;
    }
    s_info[tid] = info;
    __syncthreads();

    // Phase 2: one-hot scores, coalesced float4 stores over the block's contiguous region.
    const int nv = min(TPB, A_ - abase);                  // valid anchors in this block
    const long long i0 = (long long)b*A_ + abase;         // first global anchor
    float4* sc4 = reinterpret_cast<float4*>(out + OFF_SC) + i0 * (NC_/4);
    const int total = nv * (NC_/4);
    int local = tid / (NC_/4);
    int q     = tid - local * (NC_/4);
    for (int k = tid; k < total; k += TPB) {
        unsigned inf = s_info[local];
        int lb = (inf & 0x100u) ? (int)(inf & 0xFFu) : -1;
        int base = q * 4;
        float4 v;
        v.x = (lb == base    ) ? 1.0f : 0.0f;
        v.y = (lb == base + 1) ? 1.0f : 0.0f;
        v.z = (lb == base + 2) ? 1.0f : 0.0f;
        v.w = (lb == base + 3) ? 1.0f : 0.0f;
        sc4[k] = v;
        // advance (local, q) by TPB positions in the (anchor, quad) space
        local += TPB / (NC_/4);                            // 12
        q     += TPB - (TPB / (NC_/4)) * (NC_/4);          // 16
        if (q >= (NC_/4)) { q -= (NC_/4); local += 1; }
    }
}

extern "C" void kernel_launch(void* const* d_in, const int* in_sizes, int n_in,
                              void* d_out, int out_size) {
    // metadata order: pd_scores, pd_bboxes, anc_points, gt_labels, gt_bboxes, mask_gt
    const float* pd_bboxes = (const float*)d_in[1];
    const int*   gt_labels = (const int*)d_in[3];   // int64 -> int32 by harness
    const float* gt_bboxes = (const float*)d_in[4];
    const int*   mask_gt   = (const int*)d_in[5];
    float* out = (float*)d_out;

    dim3 gi(NBI_, BS_), ga(NB_, BS_);
    k_iou<<<gi, TPB>>>(pd_bboxes, gt_bboxes, mask_gt);
    k_fallback<<<BS_, TPB>>>(pd_bboxes, gt_bboxes, mask_gt);
    k_assign_scores<<<ga, TPB>>>(gt_labels, gt_bboxes, mask_gt, out);
}